// round 15
// baseline (speedup 1.0000x reference)
#include <cuda_runtime.h>
#include <cuda_bf16.h>
#include <cstdint>
#include <float.h>
#include <math.h>

// Problem constants
#define BB 4
#define KK 8
#define VV 32000
#define EE 512
#define HH 1024
#define TT 64
#define NR 32            // B*K rows
#define NCH 16           // k-chunks of 64 (logits)
#define NT16 2000        // m16 vocab tiles
#define NBLK 296         // logits blocks (one wave at 2/SM)

// ---------------- device scratch (static: no allocation allowed) ----------------
// packed, pre-swizzled W_out at m16 granularity: [kchunk][m16tile][hi|lo][16 x 64]
__device__ __align__(128) __nv_bfloat16 g_Wp[(size_t)NCH * NT16 * 2048];
__device__ __align__(128) __nv_bfloat16 g_Pih[(size_t)24 * 8 * 2 * 8192];
__device__ __align__(128) __nv_bfloat16 g_Phh[(size_t)24 * 16 * 2 * 8192];
__device__ __align__(128) __nv_bfloat16 g_Bp[NCH * 2 * 2048];   // h2 (for logits)
__device__ __align__(128) __nv_bfloat16 g_Xp[8 * 2 * 2048];     // emb(x) for GRU
__device__ __align__(128) __nv_bfloat16 g_Hp[16 * 2 * 2048];    // h_prev for GRU
__device__ float g_pih[2][NR][3072];
__device__ float g_phh[4][NR][3072];
__device__ float g_pvm[NR][NBLK];
__device__ float g_pvs[NR][NBLK];
__device__ float g_p8v[NR][NBLK][8];
__device__ int   g_p8i[NR][NBLK][8];
__device__ float g_hid[2][NR * HH];
__device__ float g_prevvals[NR];
__device__ int   g_prevtok[NR];
__device__ int   g_last[NR];
__device__ int   g_which[NR];
__device__ float g_lph[2][NR * TT];
__device__ int   g_tkh[2][NR * TT];

// ---------------- PTX helpers ----------------
__device__ __forceinline__ uint32_t smem_u32(const void* p) {
    return (uint32_t)__cvta_generic_to_shared(p);
}
__device__ __forceinline__ void mbar_init(uint32_t a, uint32_t cnt) {
    asm volatile("mbarrier.init.shared.b64 [%0], %1;" :: "r"(a), "r"(cnt) : "memory");
}
__device__ __forceinline__ void mbar_expect(uint32_t a, uint32_t tx) {
    asm volatile("mbarrier.arrive.expect_tx.shared.b64 _, [%0], %1;" :: "r"(a), "r"(tx) : "memory");
}
#define MBAR_WAIT(addr, parity) do {                                          \
    asm volatile("{\n\t.reg .pred P1;\n\t"                                    \
        "W_%=:\n\t"                                                           \
        "mbarrier.try_wait.parity.acquire.cta.shared::cta.b64 P1, [%0], %1, 0x989680;\n\t" \
        "@P1 bra D_%=;\n\t"                                                   \
        "bra W_%=;\n\t"                                                       \
        "D_%=:\n\t}"                                                          \
        :: "r"(addr), "r"(parity) : "memory"); } while (0)

__device__ __forceinline__ void bulkcp(uint32_t dst, const void* src, uint32_t bytes, uint32_t mbar) {
    asm volatile("cp.async.bulk.shared::cta.global.mbarrier::complete_tx::bytes [%0], [%1], %2, [%3];"
                 :: "r"(dst), "l"(src), "r"(bytes), "r"(mbar) : "memory");
}
__device__ __forceinline__ void ldm4(uint32_t a[4], uint32_t addr) {
    asm volatile("ldmatrix.sync.aligned.m8n8.x4.shared.b16 {%0,%1,%2,%3}, [%4];\n"
                 : "=r"(a[0]), "=r"(a[1]), "=r"(a[2]), "=r"(a[3]) : "r"(addr));
}
__device__ __forceinline__ void mma16816(float c[4], const uint32_t a[4], const uint32_t b[2]) {
    asm volatile("mma.sync.aligned.m16n8k16.row.col.f32.bf16.bf16.f32 "
                 "{%0,%1,%2,%3},{%4,%5,%6,%7},{%8,%9},{%0,%1,%2,%3};\n"
                 : "+f"(c[0]), "+f"(c[1]), "+f"(c[2]), "+f"(c[3])
                 : "r"(a[0]), "r"(a[1]), "r"(a[2]), "r"(a[3]), "r"(b[0]), "r"(b[1]));
}
__device__ __forceinline__ int swz(int row, int col) {
    return (row * 128 + ((col * 2) ^ ((row & 7) << 4))) >> 1;
}

// ---------------- weight pack kernels ----------------
__global__ void conv_kernel(const float* __restrict__ W) {   // W_out -> m16-granular planes
    size_t n = (size_t)VV * HH;
    for (size_t i = (size_t)blockIdx.x * blockDim.x + threadIdx.x; i < n;
         i += (size_t)gridDim.x * blockDim.x) {
        float w = W[i];
        int v = (int)(i >> 10), k = (int)(i & 1023);
        int tile = v >> 4, row = v & 15, kc = k >> 6, col = k & 63;
        size_t base = ((size_t)kc * NT16 + tile) * 2048;
        int off = swz(row, col);
        __nv_bfloat16 hi = __float2bfloat16(w);
        g_Wp[base + off] = hi;
        g_Wp[base + 1024 + off] = __float2bfloat16(w - __bfloat162float(hi));
    }
}
__global__ void wpack_ih_kernel(const float* __restrict__ W) {  // [3072 x 512]
    size_t n = (size_t)3072 * 512;
    for (size_t i = (size_t)blockIdx.x * blockDim.x + threadIdx.x; i < n;
         i += (size_t)gridDim.x * blockDim.x) {
        float w = W[i];
        int v = (int)(i >> 9), k = (int)(i & 511);
        int mt = v >> 7, row = v & 127, kc = k >> 6, col = k & 63;
        size_t base = ((size_t)mt * 8 + kc) * 2 * 8192;
        int off = swz(row, col);
        __nv_bfloat16 hi = __float2bfloat16(w);
        g_Pih[base + off] = hi;
        g_Pih[base + 8192 + off] = __float2bfloat16(w - __bfloat162float(hi));
    }
}
__global__ void wpack_hh_kernel(const float* __restrict__ W) {  // [3072 x 1024]
    size_t n = (size_t)3072 * 1024;
    for (size_t i = (size_t)blockIdx.x * blockDim.x + threadIdx.x; i < n;
         i += (size_t)gridDim.x * blockDim.x) {
        float w = W[i];
        int v = (int)(i >> 10), k = (int)(i & 1023);
        int mt = v >> 7, row = v & 127, kc = k >> 6, col = k & 63;
        size_t base = ((size_t)mt * 16 + kc) * 2 * 8192;
        int off = swz(row, col);
        __nv_bfloat16 hi = __float2bfloat16(w);
        g_Phh[base + off] = hi;
        g_Phh[base + 8192 + off] = __float2bfloat16(w - __bfloat162float(hi));
    }
}

// ---------------- init ----------------
__global__ void init_kernel(const int* __restrict__ bosp) {
    int tid = threadIdx.x;
    if (tid < NR) {
        g_last[tid]     = bosp[0];
        g_prevvals[tid] = 0.0f;
        g_prevtok[tid]  = -1;
    }
}

// ---------------- per-step 0: pack x (emb gather) and h_prev (beam gather) ----------------
__global__ __launch_bounds__(256) void pack_kernel(int t,
        const float* __restrict__ encoded, const float* __restrict__ emb) {
    for (int idx = blockIdx.x * 256 + threadIdx.x; idx < NR * (EE + HH); idx += 32 * 256) {
        if (idx < NR * EE) {
            int r = idx >> 9, e = idx & 511;
            float v = emb[(size_t)g_last[r] * EE + e];
            int kc = e >> 6, col = e & 63;
            int off = swz(r, col);
            __nv_bfloat16 hi = __float2bfloat16(v);
            g_Xp[(kc * 2 + 0) * 2048 + off] = hi;
            g_Xp[(kc * 2 + 1) * 2048 + off] = __float2bfloat16(v - __bfloat162float(hi));
        } else {
            int j = idx - NR * EE;
            int r = j >> 10, e = j & 1023;
            float v = (t == 0) ? encoded[(size_t)((r < BB) ? r : 0) * HH + e]
                               : g_hid[(t - 1) & 1][(size_t)g_which[r] * HH + e];
            int kc = e >> 6, col = e & 63;
            int off = swz(r, col);
            __nv_bfloat16 hi = __float2bfloat16(v);
            g_Hp[(kc * 2 + 0) * 2048 + off] = hi;
            g_Hp[(kc * 2 + 1) * 2048 + off] = __float2bfloat16(v - __bfloat162float(hi));
        }
    }
}

// ---------------- per-step 1: GRU GEMMs (split-bf16 TC, split-K) ----------------
#define STB 40960
#define GG_SMEM (2 * STB + 16)

__global__ __launch_bounds__(128) void grugemm_kernel() {
    extern __shared__ char smem[];
    uint32_t sbase = smem_u32(smem);
    uint32_t mbar = sbase + 2 * STB;
    int tid = threadIdx.x, warp = tid >> 5, lane = tid & 31;
    int bid = blockIdx.x;

    const __nv_bfloat16* Abase;
    const __nv_bfloat16* Bbase;
    float* outp;
    int mtile;
    if (bid < 48) {
        mtile = bid >> 1; int split = bid & 1;
        Abase = g_Pih + ((size_t)(mtile * 8 + split * 4)) * 16384;
        Bbase = g_Xp + (size_t)(split * 4) * 4096;
        outp  = &g_pih[split][0][0];
    } else {
        int q = bid - 48;
        mtile = q >> 2; int split = q & 3;
        Abase = g_Phh + ((size_t)(mtile * 16 + split * 4)) * 16384;
        Bbase = g_Hp + (size_t)(split * 4) * 4096;
        outp  = &g_phh[split][0][0];
    }

    if (tid == 0) { mbar_init(mbar, 1); mbar_init(mbar + 8, 1); }
    __syncthreads();
    if (tid == 0) {
#pragma unroll
        for (int kc = 0; kc < 2; kc++) {
            mbar_expect(mbar + kc * 8, STB);
            bulkcp(sbase + kc * STB, (const char*)Abase + (size_t)kc * 32768, 32768, mbar + kc * 8);
            bulkcp(sbase + kc * STB + 32768, (const char*)Bbase + (size_t)kc * 8192, 8192, mbar + kc * 8);
        }
    }

    float acc[2][4][4];
#pragma unroll
    for (int m = 0; m < 2; m++)
#pragma unroll
        for (int n = 0; n < 4; n++)
#pragma unroll
            for (int f = 0; f < 4; f++) acc[m][n][f] = 0.0f;

    for (int kc = 0; kc < 4; kc++) {
        int st = kc & 1;
        MBAR_WAIT(mbar + st * 8, (kc >> 1) & 1);
        uint32_t aA = sbase + st * STB;
        const char* pB = smem + st * STB + 32768;

#pragma unroll
        for (int kk = 0; kk < 4; kk++) {
            int kb = kk * 16;
            uint32_t ahi[2][4], alo[2][4];
#pragma unroll
            for (int mt = 0; mt < 2; mt++) {
                int row = warp * 32 + mt * 16 + (lane & 15);
                int colByte = (kb + ((lane >> 4) << 3)) * 2;
                uint32_t off = row * 128 + (colByte ^ ((row & 7) << 4));
                ldm4(ahi[mt], aA + off);
                ldm4(alo[mt], aA + 16384 + off);
            }
            uint32_t bhi[4][2], blo[4][2];
#pragma unroll
            for (int nt = 0; nt < 4; nt++) {
                int n = nt * 8 + (lane >> 2);
                int c0 = (kb + ((lane & 3) << 1)) * 2;
                uint32_t x = (n & 7) << 4;
                uint32_t o0 = n * 128 + (c0 ^ x);
                uint32_t o1 = n * 128 + ((c0 + 16) ^ x);
                bhi[nt][0] = *(const uint32_t*)(pB + o0);
                bhi[nt][1] = *(const uint32_t*)(pB + o1);
                blo[nt][0] = *(const uint32_t*)(pB + 4096 + o0);
                blo[nt][1] = *(const uint32_t*)(pB + 4096 + o1);
            }
#pragma unroll
            for (int mt = 0; mt < 2; mt++)
#pragma unroll
                for (int nt = 0; nt < 4; nt++) {
                    mma16816(acc[mt][nt], ahi[mt], bhi[nt]);
                    mma16816(acc[mt][nt], ahi[mt], blo[nt]);
                    mma16816(acc[mt][nt], alo[mt], bhi[nt]);
                }
        }
        __syncthreads();
        if (tid == 0 && kc + 2 < 4) {
            mbar_expect(mbar + st * 8, STB);
            bulkcp(sbase + st * STB, (const char*)Abase + (size_t)(kc + 2) * 32768, 32768, mbar + st * 8);
            bulkcp(sbase + st * STB + 32768, (const char*)Bbase + (size_t)(kc + 2) * 8192, 8192, mbar + st * 8);
        }
    }

    float* sOut = (float*)smem;   // [32][132]
#pragma unroll
    for (int mt = 0; mt < 2; mt++)
#pragma unroll
        for (int nt = 0; nt < 4; nt++) {
            int vl = warp * 32 + mt * 16 + (lane >> 2);
            int n0 = nt * 8 + ((lane & 3) << 1);
            sOut[n0 * 132 + vl]           = acc[mt][nt][0];
            sOut[(n0 + 1) * 132 + vl]     = acc[mt][nt][1];
            sOut[n0 * 132 + vl + 8]       = acc[mt][nt][2];
            sOut[(n0 + 1) * 132 + vl + 8] = acc[mt][nt][3];
        }
    __syncthreads();
#pragma unroll
    for (int i = tid; i < 32 * 128; i += 128) {
        int n = i >> 7, m = i & 127;
        outp[(size_t)n * 3072 + mtile * 128 + m] = sOut[n * 132 + m];
    }
}

// ---------------- per-step 2: GRU elementwise (gates, h2, B-pack) ----------------
__global__ __launch_bounds__(256) void gruelem_kernel(int t,
        const float* __restrict__ encoded,
        const float* __restrict__ bih, const float* __restrict__ bhh) {
    int idx = blockIdx.x * 256 + threadIdx.x;
    int r = idx >> 10, u = idx & 1023;

    float gir = g_pih[0][r][u]        + g_pih[1][r][u];
    float giz = g_pih[0][r][1024 + u] + g_pih[1][r][1024 + u];
    float gin = g_pih[0][r][2048 + u] + g_pih[1][r][2048 + u];
    float ghr = g_phh[0][r][u] + g_phh[1][r][u] + g_phh[2][r][u] + g_phh[3][r][u];
    float ghz = g_phh[0][r][1024 + u] + g_phh[1][r][1024 + u] + g_phh[2][r][1024 + u] + g_phh[3][r][1024 + u];
    float ghn = g_phh[0][r][2048 + u] + g_phh[1][r][2048 + u] + g_phh[2][r][2048 + u] + g_phh[3][r][2048 + u];

    float hprev = (t == 0) ? encoded[(size_t)((r < BB) ? r : 0) * HH + u]
                           : g_hid[(t - 1) & 1][(size_t)g_which[r] * HH + u];

    float rg = 1.0f / (1.0f + expf(-(gir + ghr + bih[u] + bhh[u])));
    float zg = 1.0f / (1.0f + expf(-(giz + ghz + bih[1024 + u] + bhh[1024 + u])));
    float ng = tanhf(gin + bih[2048 + u] + rg * (ghn + bhh[2048 + u]));
    float h2 = (1.0f - zg) * ng + zg * hprev;

    g_hid[t & 1][r * HH + u] = h2;
    int kc = u >> 6, col = u & 63;
    int off = swz(r, col);
    __nv_bfloat16 hi = __float2bfloat16(h2);
    g_Bp[(kc * 2 + 0) * 2048 + off] = hi;
    g_Bp[(kc * 2 + 1) * 2048 + off] = __float2bfloat16(h2 - __bfloat162float(hi));
}

// ---------------- top-k primitives ----------------
__device__ __forceinline__ bool betterf(float va, int ia, float vb, int ib) {
    return (va > vb) || (va == vb && ia < ib);
}
#define INS_DECL float lv[8]; int li[8]; \
    _Pragma("unroll") for (int j = 0; j < 8; j++) { lv[j] = -FLT_MAX; li[j] = 0x7FFFFFFF; }
#define INS(vx, ix) do { float _v = (vx); int _i = (ix); \
    if (betterf(_v, _i, lv[7], li[7])) { \
        bool placed = false; \
        _Pragma("unroll") for (int j = 7; j >= 1; j--) { \
            if (!placed) { \
                if (betterf(_v, _i, lv[j-1], li[j-1])) { lv[j] = lv[j-1]; li[j] = li[j-1]; } \
                else { lv[j] = _v; li[j] = _i; placed = true; } } } \
        if (!placed) { lv[0] = _v; li[0] = _i; } } } while (0)

__device__ __forceinline__ void merge_pair(float* sv, int* si, int pa, int pb) {
    float rv[8]; int ri[8]; int ia = 0, ib = 0;
#pragma unroll
    for (int j = 0; j < 8; j++) {
        float va = sv[pa + ia], vb = sv[pb + ib];
        int   xa = si[pa + ia], xb = si[pb + ib];
        bool ta = betterf(va, xa, vb, xb);
        rv[j] = ta ? va : vb; ri[j] = ta ? xa : xb;
        ia += ta; ib += !ta;
    }
#pragma unroll
    for (int j = 0; j < 8; j++) { sv[pa + j] = rv[j]; si[pa + j] = ri[j]; }
}
__device__ __forceinline__ void merge_lists(float* sv, int* si, int tid, int nfirst) {
    for (int off = nfirst; off >= 1; off >>= 1) {
        if (tid < off) merge_pair(sv, si, tid * 8, (tid + off) * 8);
        __syncthreads();
    }
}

// ---------------- per-step 3: logits GEMM + fused stats; uniform-work grid=296 ----------------
// Block bid owns cnt (7 or 6) m16 vocab tiles starting at tile `start`.
// Stage = A (<=28672B, contiguous m16 planes) + B (8192B). 2-stage ring, 2 blocks/SM.
#define ASTG 28672
#define STB2 (ASTG + 8192)            // 36864
#define LG_SMEM (2 * STB2 + 16)       // 73744

__global__ __launch_bounds__(128) void logits_kernel(const float* __restrict__ b_out) {
    extern __shared__ char smem[];
    uint32_t sbase = smem_u32(smem);
    uint32_t mbar = sbase + 2 * STB2;
    int tid = threadIdx.x, warp = tid >> 5, lane = tid & 31;
    int bid = blockIdx.x;
    int cnt   = (bid < 224) ? 7 : 6;
    int start = (bid < 224) ? bid * 7 : 1568 + (bid - 224) * 6;
    uint32_t abytes = (uint32_t)cnt * 4096;

    if (tid == 0) { mbar_init(mbar, 1); mbar_init(mbar + 8, 1); }
    __syncthreads();
    if (tid == 0) {
#pragma unroll
        for (int kc = 0; kc < 2; kc++) {
            mbar_expect(mbar + kc * 8, abytes + 8192);
            bulkcp(sbase + kc * STB2,
                   (const char*)g_Wp + ((size_t)kc * NT16 + start) * 4096, abytes, mbar + kc * 8);
            bulkcp(sbase + kc * STB2 + ASTG, (const char*)g_Bp + kc * 8192, 8192, mbar + kc * 8);
        }
    }

    float acc[2][4][4];
#pragma unroll
    for (int m = 0; m < 2; m++)
#pragma unroll
        for (int n = 0; n < 4; n++)
#pragma unroll
            for (int f = 0; f < 4; f++) acc[m][n][f] = 0.0f;

    for (int kc = 0; kc < NCH; kc++) {
        int st = kc & 1;
        MBAR_WAIT(mbar + st * 8, (kc >> 1) & 1);
        uint32_t aA = sbase + st * STB2;
        const char* pB = smem + st * STB2 + ASTG;

#pragma unroll
        for (int kk = 0; kk < 4; kk++) {
            int kb = kk * 16;
            uint32_t ahi[2][4], alo[2][4];
#pragma unroll
            for (int mt = 0; mt < 2; mt++) {
                int lt = warp + mt * 4;
                if (lt < cnt) {
                    int row = lane & 15;
                    int colByte = (kb + ((lane >> 4) << 3)) * 2;
                    uint32_t off = (uint32_t)lt * 4096 + row * 128 + (colByte ^ ((row & 7) << 4));
                    ldm4(ahi[mt], aA + off);
                    ldm4(alo[mt], aA + 2048 + off);
                }
            }
            uint32_t bhi[4][2], blo[4][2];
#pragma unroll
            for (int nt = 0; nt < 4; nt++) {
                int n = nt * 8 + (lane >> 2);
                int c0 = (kb + ((lane & 3) << 1)) * 2;
                uint32_t x = (n & 7) << 4;
                uint32_t o0 = n * 128 + (c0 ^ x);
                uint32_t o1 = n * 128 + ((c0 + 16) ^ x);
                bhi[nt][0] = *(const uint32_t*)(pB + o0);
                bhi[nt][1] = *(const uint32_t*)(pB + o1);
                blo[nt][0] = *(const uint32_t*)(pB + 4096 + o0);
                blo[nt][1] = *(const uint32_t*)(pB + 4096 + o1);
            }
#pragma unroll
            for (int mt = 0; mt < 2; mt++) {
                if (warp + mt * 4 < cnt) {
#pragma unroll
                    for (int nt = 0; nt < 4; nt++) {
                        mma16816(acc[mt][nt], ahi[mt], bhi[nt]);
                        mma16816(acc[mt][nt], ahi[mt], blo[nt]);
                        mma16816(acc[mt][nt], alo[mt], bhi[nt]);
                    }
                }
            }
        }
        __syncthreads();
        if (tid == 0 && kc + 2 < NCH) {
            mbar_expect(mbar + st * 8, abytes + 8192);
            bulkcp(sbase + st * STB2,
                   (const char*)g_Wp + ((size_t)(kc + 2) * NT16 + start) * 4096, abytes, mbar + st * 8);
            bulkcp(sbase + st * STB2 + ASTG, (const char*)g_Bp + (kc + 2) * 8192, 8192, mbar + st * 8);
        }
    }

    // fused epilogue: transpose to [32][<=112] + per-(row,block) stats
    float* sOut  = (float*)smem;        // [32][116]
    float* sBias = sOut + 32 * 116;     // [112]
    float* svv   = sBias + 112;         // [128*8]
    int*   sii   = (int*)(svv + 1024);  // [128*8]
    int ccnt = cnt * 16;
    int vstart = start * 16;
    for (int c = tid; c < ccnt; c += 128) sBias[c] = b_out[vstart + c];
#pragma unroll
    for (int mt = 0; mt < 2; mt++) {
        int lt = warp + mt * 4;
        if (lt < cnt) {
#pragma unroll
            for (int nt = 0; nt < 4; nt++) {
                int vl = lt * 16 + (lane >> 2);
                int n0 = nt * 8 + ((lane & 3) << 1);
                sOut[n0 * 116 + vl]           = acc[mt][nt][0];
                sOut[(n0 + 1) * 116 + vl]     = acc[mt][nt][1];
                sOut[n0 * 116 + vl + 8]       = acc[mt][nt][2];
                sOut[(n0 + 1) * 116 + vl + 8] = acc[mt][nt][3];
            }
        }
    }
    __syncthreads();

    int row = tid >> 2, sub = tid & 3;
    int cper = (ccnt + 3) >> 2;   // 28 or 24
    int c0 = sub * cper;
    float m = -FLT_MAX;
    for (int j = 0; j < cper; j++) {
        int c = c0 + j;
        if (c < ccnt) m = fmaxf(m, sOut[row * 116 + c] + sBias[c]);
    }
    m = fmaxf(m, __shfl_xor_sync(0xFFFFFFFFu, m, 1));
    m = fmaxf(m, __shfl_xor_sync(0xFFFFFFFFu, m, 2));
    float ssum = 0.f;
    INS_DECL
    for (int j = 0; j < cper; j++) {
        int c = c0 + j;
        if (c < ccnt) {
            float v = sOut[row * 116 + c] + sBias[c];
            ssum += __expf(v - m);
            INS(v, vstart + c);
        }
    }
    ssum += __shfl_xor_sync(0xFFFFFFFFu, ssum, 1);
    ssum += __shfl_xor_sync(0xFFFFFFFFu, ssum, 2);
#pragma unroll
    for (int j = 0; j < 8; j++) { svv[tid * 8 + j] = lv[j]; sii[tid * 8 + j] = li[j]; }
    __syncwarp();
    if (sub < 2) merge_pair(svv, sii, tid * 8, (tid + 2) * 8);
    __syncwarp();
    if (sub < 1) merge_pair(svv, sii, tid * 8, (tid + 1) * 8);
    __syncwarp();
    if (sub == 0) {
        g_pvm[row][bid] = m;
        g_pvs[row][bid] = ssum;
#pragma unroll
        for (int j = 0; j < 8; j++) {
            g_p8v[row][bid][j] = svv[tid * 8 + j];
            g_p8i[row][bid][j] = sii[tid * 8 + j];
        }
    }
}

// ---------------- per-step 4: merge (LSE + top-8 + beam update + history) ----------------
__global__ __launch_bounds__(256) void merge_kernel(int t, const int* __restrict__ eosp) {
    __shared__ float sv[2048]; __shared__ int si[2048];
    __shared__ float s_val[8]; __shared__ int s_tok[8], s_wk[8];
    int b = blockIdx.x, tid = threadIdx.x;
    int s = tid >> 5, lane = tid & 31;
    int eos = eosp[0];

    INS_DECL
    if (t == 0) {
        if (s == 0) {
            int row = b;
            float M = -FLT_MAX;
            for (int vt = lane; vt < NBLK; vt += 32) M = fmaxf(M, g_pvm[row][vt]);
#pragma unroll
            for (int o = 16; o >= 1; o >>= 1) M = fmaxf(M, __shfl_xor_sync(0xFFFFFFFFu, M, o));
            float S = 0.f;
            for (int vt = lane; vt < NBLK; vt += 32) S += g_pvs[row][vt] * __expf(g_pvm[row][vt] - M);
#pragma unroll
            for (int o = 16; o >= 1; o >>= 1) S += __shfl_xor_sync(0xFFFFFFFFu, S, o);
            float rc = -(M + logf(S));
            for (int vt = lane; vt < NBLK; vt += 32)
#pragma unroll
                for (int j = 0; j < 8; j++) INS(g_p8v[row][vt][j] + rc, g_p8i[row][vt][j]);
        }
    } else {
        int row = b * 8 + s;
        float M = -FLT_MAX;
        for (int vt = lane; vt < NBLK; vt += 32) M = fmaxf(M, g_pvm[row][vt]);
#pragma unroll
        for (int o = 16; o >= 1; o >>= 1) M = fmaxf(M, __shfl_xor_sync(0xFFFFFFFFu, M, o));
        float S = 0.f;
        for (int vt = lane; vt < NBLK; vt += 32) S += g_pvs[row][vt] * __expf(g_pvm[row][vt] - M);
#pragma unroll
        for (int o = 16; o >= 1; o >>= 1) S += __shfl_xor_sync(0xFFFFFFFFu, S, o);
        float rc = g_prevvals[row] - (M + logf(S));
        if (g_prevtok[row] == eos) {
            if (lane == 0) INS(0.0f, s * VV + eos);
        } else {
            for (int vt = lane; vt < NBLK; vt += 32)
#pragma unroll
                for (int j = 0; j < 8; j++) INS(g_p8v[row][vt][j] + rc, s * VV + g_p8i[row][vt][j]);
        }
    }
#pragma unroll
    for (int j = 0; j < 8; j++) { sv[tid * 8 + j] = lv[j]; si[tid * 8 + j] = li[j]; }
    __syncthreads();
    merge_lists(sv, si, tid, 128);

    if (tid < 8) {
        float v = sv[tid]; int id = si[tid];
        int tok = (t == 0) ? id : (id % VV);
        int wk  = (t == 0) ? 0  : (id / VV);
        s_val[tid] = v; s_tok[tid] = tok; s_wk[tid] = wk;
        int row = b * 8 + tid;
        g_prevvals[row] = v; g_prevtok[row] = tok; g_last[row] = tok;
        g_which[row] = (t == 0) ? b : (b * 8 + wk);
    }
    __syncthreads();

    if (t == 0) {
        for (int i = tid; i < 8 * TT; i += 256) {
            int k = i >> 6, st = i & 63;
            g_lph[0][(b * 8 + k) * TT + st] = (st == 0) ? s_val[k] : 0.0f;
            g_tkh[0][(b * 8 + k) * TT + st] = (st == 0) ? s_tok[k] : 0;
        }
    } else {
        int nb = t & 1, ob = nb ^ 1;
        for (int i = tid; i < 8 * TT; i += 256) {
            int k = i >> 6, st = i & 63;
            int dst = (b * 8 + k) * TT + st;
            int srcrow = b * 8 + s_wk[k];
            float lp; int tk;
            if (st < t)       { lp = g_lph[ob][srcrow * TT + st]; tk = g_tkh[ob][srcrow * TT + st]; }
            else if (st == t) { lp = s_val[k]; tk = s_tok[k]; }
            else              { lp = 0.0f;     tk = 0; }
            g_lph[nb][dst] = lp; g_tkh[nb][dst] = tk;
        }
    }
}

// ---------------- output ----------------
__global__ void fin_kernel(float* __restrict__ out, int n) {
    int i = blockIdx.x * blockDim.x + threadIdx.x;
    if (i >= n) return;
    if (i < NR * TT)          out[i] = g_lph[1][i];
    else if (i < 2 * NR * TT) out[i] = (float)g_tkh[1][i - NR * TT];
    else                      out[i] = 0.0f;
}

// ---------------- launch ----------------
extern "C" void kernel_launch(void* const* d_in, const int* in_sizes, int n_in,
                              void* d_out, int out_size) {
    const float* encoded   = (const float*)d_in[0];
    const float* embedding = (const float*)d_in[1];
    const float* W_ih      = (const float*)d_in[2];
    const float* W_hh      = (const float*)d_in[3];
    const float* b_ih      = (const float*)d_in[4];
    const float* b_hh      = (const float*)d_in[5];
    const float* W_out     = (const float*)d_in[6];
    const float* b_out     = (const float*)d_in[7];
    const int*   bos       = (const int*)d_in[8];
    const int*   eos       = (const int*)d_in[9];

    cudaFuncSetAttribute(logits_kernel,  cudaFuncAttributeMaxDynamicSharedMemorySize, LG_SMEM);
    cudaFuncSetAttribute(grugemm_kernel, cudaFuncAttributeMaxDynamicSharedMemorySize, GG_SMEM);

    conv_kernel<<<1024, 256>>>(W_out);
    wpack_ih_kernel<<<512, 256>>>(W_ih);
    wpack_hh_kernel<<<1024, 256>>>(W_hh);
    init_kernel<<<1, 32>>>(bos);

    for (int t = 0; t < TT; t++) {
        pack_kernel<<<32, 256>>>(t, encoded, embedding);
        grugemm_kernel<<<144, 128, GG_SMEM>>>();
        gruelem_kernel<<<128, 256>>>(t, encoded, b_ih, b_hh);
        logits_kernel<<<NBLK, 128, LG_SMEM>>>(b_out);
        merge_kernel<<<BB, 256>>>(t, eos);
    }
    fin_kernel<<<(out_size + 255) / 256, 256>>>((float*)d_out, out_size);
}

// round 16
// speedup vs baseline: 1.4230x; 1.4230x over previous
#include <cuda_runtime.h>
#include <cuda_bf16.h>
#include <cstdint>
#include <float.h>
#include <math.h>

// Problem constants
#define BB 4
#define KK 8
#define VV 32000
#define EE 512
#define HH 1024
#define TT 64
#define NR 32            // B*K rows
#define NVT 250          // vocab tiles of 128
#define NCH 16           // k-chunks of 64 (logits)

// ---------------- device scratch (static: no allocation allowed) ----------------
// packed, pre-swizzled W_out: [vtile][kchunk][hi|lo][128 x 64] bf16
__device__ __align__(128) __nv_bfloat16 g_Wp[(size_t)NVT * NCH * 2 * 8192];
__device__ __align__(128) __nv_bfloat16 g_Pih[(size_t)24 * 8 * 2 * 8192];
__device__ __align__(128) __nv_bfloat16 g_Phh[(size_t)24 * 16 * 2 * 8192];
__device__ __align__(128) __nv_bfloat16 g_Bp[NCH * 2 * 2048];   // h2 (for logits)
__device__ float g_pih[2][NR][3072];
__device__ float g_phh[4][NR][3072];
__device__ float g_pvm[NR][NVT];
__device__ float g_pvs[NR][NVT];
__device__ float g_p8v[NR][NVT][8];
__device__ int   g_p8i[NR][NVT][8];
__device__ float g_hid[2][NR * HH];
__device__ float g_prevvals[NR];
__device__ int   g_prevtok[NR];
__device__ int   g_last[NR];
__device__ int   g_which[NR];
__device__ float g_lph[2][NR * TT];
__device__ int   g_tkh[2][NR * TT];

// ---------------- PTX helpers ----------------
__device__ __forceinline__ uint32_t smem_u32(const void* p) {
    return (uint32_t)__cvta_generic_to_shared(p);
}
__device__ __forceinline__ void mbar_init(uint32_t a, uint32_t cnt) {
    asm volatile("mbarrier.init.shared.b64 [%0], %1;" :: "r"(a), "r"(cnt) : "memory");
}
__device__ __forceinline__ void mbar_expect(uint32_t a, uint32_t tx) {
    asm volatile("mbarrier.arrive.expect_tx.shared.b64 _, [%0], %1;" :: "r"(a), "r"(tx) : "memory");
}
#define MBAR_WAIT(addr, parity) do {                                          \
    asm volatile("{\n\t.reg .pred P1;\n\t"                                    \
        "W_%=:\n\t"                                                           \
        "mbarrier.try_wait.parity.acquire.cta.shared::cta.b64 P1, [%0], %1, 0x989680;\n\t" \
        "@P1 bra D_%=;\n\t"                                                   \
        "bra W_%=;\n\t"                                                       \
        "D_%=:\n\t}"                                                          \
        :: "r"(addr), "r"(parity) : "memory"); } while (0)

__device__ __forceinline__ void bulkcp(uint32_t dst, const void* src, uint32_t bytes, uint32_t mbar) {
    asm volatile("cp.async.bulk.shared::cta.global.mbarrier::complete_tx::bytes [%0], [%1], %2, [%3];"
                 :: "r"(dst), "l"(src), "r"(bytes), "r"(mbar) : "memory");
}
__device__ __forceinline__ void ldm4(uint32_t a[4], uint32_t addr) {
    asm volatile("ldmatrix.sync.aligned.m8n8.x4.shared.b16 {%0,%1,%2,%3}, [%4];\n"
                 : "=r"(a[0]), "=r"(a[1]), "=r"(a[2]), "=r"(a[3]) : "r"(addr));
}
__device__ __forceinline__ void mma16816(float c[4], const uint32_t a[4], const uint32_t b[2]) {
    asm volatile("mma.sync.aligned.m16n8k16.row.col.f32.bf16.bf16.f32 "
                 "{%0,%1,%2,%3},{%4,%5,%6,%7},{%8,%9},{%0,%1,%2,%3};\n"
                 : "+f"(c[0]), "+f"(c[1]), "+f"(c[2]), "+f"(c[3])
                 : "r"(a[0]), "r"(a[1]), "r"(a[2]), "r"(a[3]), "r"(b[0]), "r"(b[1]));
}
__device__ __forceinline__ int swz(int row, int col) {
    return (row * 128 + ((col * 2) ^ ((row & 7) << 4))) >> 1;
}

// ---------------- weight pack kernels ----------------
__global__ void conv_kernel(const float* __restrict__ W) {   // W_out
    size_t n = (size_t)VV * HH;
    for (size_t i = (size_t)blockIdx.x * blockDim.x + threadIdx.x; i < n;
         i += (size_t)gridDim.x * blockDim.x) {
        float w = W[i];
        int v = (int)(i >> 10), k = (int)(i & 1023);
        int vt = v >> 7, row = v & 127, kc = k >> 6, col = k & 63;
        size_t base = ((size_t)vt * NCH + kc) * 2 * 8192;
        int off = swz(row, col);
        __nv_bfloat16 hi = __float2bfloat16(w);
        g_Wp[base + off] = hi;
        g_Wp[base + 8192 + off] = __float2bfloat16(w - __bfloat162float(hi));
    }
}
__global__ void wpack_ih_kernel(const float* __restrict__ W) {  // [3072 x 512]
    size_t n = (size_t)3072 * 512;
    for (size_t i = (size_t)blockIdx.x * blockDim.x + threadIdx.x; i < n;
         i += (size_t)gridDim.x * blockDim.x) {
        float w = W[i];
        int v = (int)(i >> 9), k = (int)(i & 511);
        int mt = v >> 7, row = v & 127, kc = k >> 6, col = k & 63;
        size_t base = ((size_t)mt * 8 + kc) * 2 * 8192;
        int off = swz(row, col);
        __nv_bfloat16 hi = __float2bfloat16(w);
        g_Pih[base + off] = hi;
        g_Pih[base + 8192 + off] = __float2bfloat16(w - __bfloat162float(hi));
    }
}
__global__ void wpack_hh_kernel(const float* __restrict__ W) {  // [3072 x 1024]
    size_t n = (size_t)3072 * 1024;
    for (size_t i = (size_t)blockIdx.x * blockDim.x + threadIdx.x; i < n;
         i += (size_t)gridDim.x * blockDim.x) {
        float w = W[i];
        int v = (int)(i >> 10), k = (int)(i & 1023);
        int mt = v >> 7, row = v & 127, kc = k >> 6, col = k & 63;
        size_t base = ((size_t)mt * 16 + kc) * 2 * 8192;
        int off = swz(row, col);
        __nv_bfloat16 hi = __float2bfloat16(w);
        g_Phh[base + off] = hi;
        g_Phh[base + 8192 + off] = __float2bfloat16(w - __bfloat162float(hi));
    }
}

// ---------------- init ----------------
__global__ void init_kernel(const int* __restrict__ bosp) {
    int tid = threadIdx.x;
    if (tid < NR) {
        g_last[tid]     = bosp[0];
        g_prevvals[tid] = 0.0f;
        g_prevtok[tid]  = -1;
    }
}

// ---------------- per-step 1: GRU GEMMs with in-block B build (fused pack) ----------------
// A: 2-stage bulk-copy ring (32KB stages). B: built in smem from emb/hidden gather.
#define ASTB 32768
#define GB_OFF (2 * ASTB)
#define GG_SMEM (2 * ASTB + 32768 + 16)   // A ring + B (4 chunks x 8KB) + mbarriers

__global__ __launch_bounds__(128) void grugemm_kernel(int t,
        const float* __restrict__ encoded, const float* __restrict__ emb) {
    extern __shared__ char smem[];
    uint32_t sbase = smem_u32(smem);
    uint32_t mbar = sbase + GB_OFF + 32768;
    int tid = threadIdx.x, warp = tid >> 5, lane = tid & 31;
    int bid = blockIdx.x;

    const __nv_bfloat16* Abase;
    float* outp;
    int mtile, split;
    bool isX;
    if (bid < 48) {
        isX = true; mtile = bid >> 1; split = bid & 1;
        Abase = g_Pih + ((size_t)(mtile * 8 + split * 4)) * 16384;
        outp  = &g_pih[split][0][0];
    } else {
        isX = false; int q = bid - 48; mtile = q >> 2; split = q & 3;
        Abase = g_Phh + ((size_t)(mtile * 16 + split * 4)) * 16384;
        outp  = &g_phh[split][0][0];
    }

    if (tid == 0) { mbar_init(mbar, 1); mbar_init(mbar + 8, 1); }
    __syncthreads();
    if (tid == 0) {
#pragma unroll
        for (int kc = 0; kc < 2; kc++) {
            mbar_expect(mbar + kc * 8, ASTB);
            bulkcp(sbase + kc * ASTB, (const char*)Abase + (size_t)kc * 32768, 32768, mbar + kc * 8);
        }
    }

    // build this block's B operand (32 rows x 256 cols, split-bf16, swizzled) in smem
    __nv_bfloat16* sB = (__nv_bfloat16*)(smem + GB_OFF);
    for (int i = tid; i < 32 * 256; i += 128) {
        int r = i >> 8, c = i & 255;
        float v;
        if (isX) {
            v = emb[(size_t)g_last[r] * EE + split * 256 + c];
        } else {
            int e = split * 256 + c;
            v = (t == 0) ? encoded[(size_t)((r < BB) ? r : 0) * HH + e]
                         : g_hid[(t - 1) & 1][(size_t)g_which[r] * HH + e];
        }
        int kcl = c >> 6, col = c & 63;
        int off = swz(r, col);
        __nv_bfloat16 hi = __float2bfloat16(v);
        sB[(kcl * 2 + 0) * 2048 + off] = hi;
        sB[(kcl * 2 + 1) * 2048 + off] = __float2bfloat16(v - __bfloat162float(hi));
    }
    __syncthreads();

    float acc[2][4][4];
#pragma unroll
    for (int m = 0; m < 2; m++)
#pragma unroll
        for (int n = 0; n < 4; n++)
#pragma unroll
            for (int f = 0; f < 4; f++) acc[m][n][f] = 0.0f;

    for (int kc = 0; kc < 4; kc++) {
        int st = kc & 1;
        MBAR_WAIT(mbar + st * 8, (kc >> 1) & 1);
        uint32_t aA = sbase + st * ASTB;
        const char* pB = smem + GB_OFF + kc * 8192;

#pragma unroll
        for (int kk = 0; kk < 4; kk++) {
            int kb = kk * 16;
            uint32_t ahi[2][4], alo[2][4];
#pragma unroll
            for (int mt = 0; mt < 2; mt++) {
                int row = warp * 32 + mt * 16 + (lane & 15);
                int colByte = (kb + ((lane >> 4) << 3)) * 2;
                uint32_t off = row * 128 + (colByte ^ ((row & 7) << 4));
                ldm4(ahi[mt], aA + off);
                ldm4(alo[mt], aA + 16384 + off);
            }
            uint32_t bhi[4][2], blo[4][2];
#pragma unroll
            for (int nt = 0; nt < 4; nt++) {
                int n = nt * 8 + (lane >> 2);
                int c0 = (kb + ((lane & 3) << 1)) * 2;
                uint32_t x = (n & 7) << 4;
                uint32_t o0 = n * 128 + (c0 ^ x);
                uint32_t o1 = n * 128 + ((c0 + 16) ^ x);
                bhi[nt][0] = *(const uint32_t*)(pB + o0);
                bhi[nt][1] = *(const uint32_t*)(pB + o1);
                blo[nt][0] = *(const uint32_t*)(pB + 4096 + o0);
                blo[nt][1] = *(const uint32_t*)(pB + 4096 + o1);
            }
#pragma unroll
            for (int mt = 0; mt < 2; mt++)
#pragma unroll
                for (int nt = 0; nt < 4; nt++) {
                    mma16816(acc[mt][nt], ahi[mt], bhi[nt]);
                    mma16816(acc[mt][nt], ahi[mt], blo[nt]);
                    mma16816(acc[mt][nt], alo[mt], bhi[nt]);
                }
        }
        __syncthreads();
        if (tid == 0 && kc + 2 < 4) {
            mbar_expect(mbar + st * 8, ASTB);
            bulkcp(sbase + st * ASTB, (const char*)Abase + (size_t)(kc + 2) * 32768, 32768, mbar + st * 8);
        }
    }

    float* sOut = (float*)smem;   // [32][132] (A ring region, all chunks consumed)
#pragma unroll
    for (int mt = 0; mt < 2; mt++)
#pragma unroll
        for (int nt = 0; nt < 4; nt++) {
            int vl = warp * 32 + mt * 16 + (lane >> 2);
            int n0 = nt * 8 + ((lane & 3) << 1);
            sOut[n0 * 132 + vl]           = acc[mt][nt][0];
            sOut[(n0 + 1) * 132 + vl]     = acc[mt][nt][1];
            sOut[n0 * 132 + vl + 8]       = acc[mt][nt][2];
            sOut[(n0 + 1) * 132 + vl + 8] = acc[mt][nt][3];
        }
    __syncthreads();
#pragma unroll
    for (int i = tid; i < 32 * 128; i += 128) {
        int n = i >> 7, m = i & 127;
        outp[(size_t)n * 3072 + mtile * 128 + m] = sOut[n * 132 + m];
    }
}

// ---------------- per-step 2: GRU elementwise (gates, h2, B-pack for logits) ----------------
__global__ __launch_bounds__(256) void gruelem_kernel(int t,
        const float* __restrict__ encoded,
        const float* __restrict__ bih, const float* __restrict__ bhh) {
    int idx = blockIdx.x * 256 + threadIdx.x;
    int r = idx >> 10, u = idx & 1023;

    float gir = g_pih[0][r][u]        + g_pih[1][r][u];
    float giz = g_pih[0][r][1024 + u] + g_pih[1][r][1024 + u];
    float gin = g_pih[0][r][2048 + u] + g_pih[1][r][2048 + u];
    float ghr = g_phh[0][r][u] + g_phh[1][r][u] + g_phh[2][r][u] + g_phh[3][r][u];
    float ghz = g_phh[0][r][1024 + u] + g_phh[1][r][1024 + u] + g_phh[2][r][1024 + u] + g_phh[3][r][1024 + u];
    float ghn = g_phh[0][r][2048 + u] + g_phh[1][r][2048 + u] + g_phh[2][r][2048 + u] + g_phh[3][r][2048 + u];

    float hprev = (t == 0) ? encoded[(size_t)((r < BB) ? r : 0) * HH + u]
                           : g_hid[(t - 1) & 1][(size_t)g_which[r] * HH + u];

    float rg = 1.0f / (1.0f + expf(-(gir + ghr + bih[u] + bhh[u])));
    float zg = 1.0f / (1.0f + expf(-(giz + ghz + bih[1024 + u] + bhh[1024 + u])));
    float ng = tanhf(gin + bih[2048 + u] + rg * (ghn + bhh[2048 + u]));
    float h2 = (1.0f - zg) * ng + zg * hprev;

    g_hid[t & 1][r * HH + u] = h2;
    int kc = u >> 6, col = u & 63;
    int off = swz(r, col);
    __nv_bfloat16 hi = __float2bfloat16(h2);
    g_Bp[(kc * 2 + 0) * 2048 + off] = hi;
    g_Bp[(kc * 2 + 1) * 2048 + off] = __float2bfloat16(h2 - __bfloat162float(hi));
}

// ---------------- top-k primitives ----------------
__device__ __forceinline__ bool betterf(float va, int ia, float vb, int ib) {
    return (va > vb) || (va == vb && ia < ib);
}
#define INS_DECL float lv[8]; int li[8]; \
    _Pragma("unroll") for (int j = 0; j < 8; j++) { lv[j] = -FLT_MAX; li[j] = 0x7FFFFFFF; }
#define INS(vx, ix) do { float _v = (vx); int _i = (ix); \
    if (betterf(_v, _i, lv[7], li[7])) { \
        bool placed = false; \
        _Pragma("unroll") for (int j = 7; j >= 1; j--) { \
            if (!placed) { \
                if (betterf(_v, _i, lv[j-1], li[j-1])) { lv[j] = lv[j-1]; li[j] = li[j-1]; } \
                else { lv[j] = _v; li[j] = _i; placed = true; } } } \
        if (!placed) { lv[0] = _v; li[0] = _i; } } } while (0)

__device__ __forceinline__ void merge_pair(float* sv, int* si, int pa, int pb) {
    float rv[8]; int ri[8]; int ia = 0, ib = 0;
#pragma unroll
    for (int j = 0; j < 8; j++) {
        float va = sv[pa + ia], vb = sv[pb + ib];
        int   xa = si[pa + ia], xb = si[pb + ib];
        bool ta = betterf(va, xa, vb, xb);
        rv[j] = ta ? va : vb; ri[j] = ta ? xa : xb;
        ia += ta; ib += !ta;
    }
#pragma unroll
    for (int j = 0; j < 8; j++) { sv[pa + j] = rv[j]; si[pa + j] = ri[j]; }
}
__device__ __forceinline__ void merge_lists(float* sv, int* si, int tid, int nfirst) {
    for (int off = nfirst; off >= 1; off >>= 1) {
        if (tid < off) merge_pair(sv, si, tid * 8, (tid + off) * 8);
        __syncthreads();
    }
}

// ---------------- per-step 3: logits GEMM + fused stats (R10 config: grid 250, 128 thr) ----------------
#define STB 40960
#define LG_SMEM (2 * STB + 16)

__global__ __launch_bounds__(128) void logits_kernel(const float* __restrict__ b_out) {
    extern __shared__ char smem[];
    uint32_t sbase = smem_u32(smem);
    uint32_t mbar = sbase + 2 * STB;
    int tid = threadIdx.x, warp = tid >> 5, lane = tid & 31;
    int v0 = blockIdx.x * 128;

    if (tid == 0) { mbar_init(mbar, 1); mbar_init(mbar + 8, 1); }
    __syncthreads();
    if (tid == 0) {
#pragma unroll
        for (int kc = 0; kc < 2; kc++) {
            mbar_expect(mbar + kc * 8, STB);
            bulkcp(sbase + kc * STB,
                   (const char*)g_Wp + ((size_t)blockIdx.x * NCH + kc) * 32768, 32768,
                   mbar + kc * 8);
            bulkcp(sbase + kc * STB + 32768, (const char*)g_Bp + kc * 8192, 8192, mbar + kc * 8);
        }
    }

    float acc[2][4][4];
#pragma unroll
    for (int m = 0; m < 2; m++)
#pragma unroll
        for (int n = 0; n < 4; n++)
#pragma unroll
            for (int f = 0; f < 4; f++) acc[m][n][f] = 0.0f;

    for (int kc = 0; kc < NCH; kc++) {
        int st = kc & 1;
        MBAR_WAIT(mbar + st * 8, (kc >> 1) & 1);
        uint32_t aA = sbase + st * STB;
        const char* pB = smem + st * STB + 32768;

#pragma unroll
        for (int kk = 0; kk < 4; kk++) {
            int kb = kk * 16;
            uint32_t ahi[2][4], alo[2][4];
#pragma unroll
            for (int mt = 0; mt < 2; mt++) {
                int row = warp * 32 + mt * 16 + (lane & 15);
                int colByte = (kb + ((lane >> 4) << 3)) * 2;
                uint32_t off = row * 128 + (colByte ^ ((row & 7) << 4));
                ldm4(ahi[mt], aA + off);
                ldm4(alo[mt], aA + 16384 + off);
            }
            uint32_t bhi[4][2], blo[4][2];
#pragma unroll
            for (int nt = 0; nt < 4; nt++) {
                int n = nt * 8 + (lane >> 2);
                int c0 = (kb + ((lane & 3) << 1)) * 2;
                uint32_t x = (n & 7) << 4;
                uint32_t o0 = n * 128 + (c0 ^ x);
                uint32_t o1 = n * 128 + ((c0 + 16) ^ x);
                bhi[nt][0] = *(const uint32_t*)(pB + o0);
                bhi[nt][1] = *(const uint32_t*)(pB + o1);
                blo[nt][0] = *(const uint32_t*)(pB + 4096 + o0);
                blo[nt][1] = *(const uint32_t*)(pB + 4096 + o1);
            }
#pragma unroll
            for (int mt = 0; mt < 2; mt++)
#pragma unroll
                for (int nt = 0; nt < 4; nt++) {
                    mma16816(acc[mt][nt], ahi[mt], bhi[nt]);
                    mma16816(acc[mt][nt], ahi[mt], blo[nt]);
                    mma16816(acc[mt][nt], alo[mt], bhi[nt]);
                }
        }
        __syncthreads();
        if (tid == 0 && kc + 2 < NCH) {
            mbar_expect(mbar + st * 8, STB);
            bulkcp(sbase + st * STB,
                   (const char*)g_Wp + ((size_t)blockIdx.x * NCH + kc + 2) * 32768, 32768,
                   mbar + st * 8);
            bulkcp(sbase + st * STB + 32768, (const char*)g_Bp + (kc + 2) * 8192, 8192, mbar + st * 8);
        }
    }

    // fused epilogue: stats per (row, vtile), no logits store
    float* sOut  = (float*)smem;        // [32][132]
    float* sBias = sOut + 32 * 132;     // [128]
    float* svv   = sBias + 128;         // [128*8]
    int*   sii   = (int*)(svv + 1024);  // [128*8]
    sBias[tid] = b_out[v0 + tid];
#pragma unroll
    for (int mt = 0; mt < 2; mt++)
#pragma unroll
        for (int nt = 0; nt < 4; nt++) {
            int vl = warp * 32 + mt * 16 + (lane >> 2);
            int n0 = nt * 8 + ((lane & 3) << 1);
            sOut[n0 * 132 + vl]           = acc[mt][nt][0];
            sOut[(n0 + 1) * 132 + vl]     = acc[mt][nt][1];
            sOut[n0 * 132 + vl + 8]       = acc[mt][nt][2];
            sOut[(n0 + 1) * 132 + vl + 8] = acc[mt][nt][3];
        }
    __syncthreads();

    int row = tid >> 2, sub = tid & 3, vl0 = sub * 32;
    float m = -FLT_MAX;
#pragma unroll 8
    for (int j = 0; j < 32; j++) m = fmaxf(m, sOut[row * 132 + vl0 + j] + sBias[vl0 + j]);
    m = fmaxf(m, __shfl_xor_sync(0xFFFFFFFFu, m, 1));
    m = fmaxf(m, __shfl_xor_sync(0xFFFFFFFFu, m, 2));
    float ssum = 0.f;
    INS_DECL
#pragma unroll 8
    for (int j = 0; j < 32; j++) {
        float v = sOut[row * 132 + vl0 + j] + sBias[vl0 + j];
        ssum += __expf(v - m);
        INS(v, v0 + vl0 + j);
    }
    ssum += __shfl_xor_sync(0xFFFFFFFFu, ssum, 1);
    ssum += __shfl_xor_sync(0xFFFFFFFFu, ssum, 2);
#pragma unroll
    for (int j = 0; j < 8; j++) { svv[tid * 8 + j] = lv[j]; sii[tid * 8 + j] = li[j]; }
    __syncwarp();
    if (sub < 2) merge_pair(svv, sii, tid * 8, (tid + 2) * 8);
    __syncwarp();
    if (sub < 1) merge_pair(svv, sii, tid * 8, (tid + 1) * 8);
    __syncwarp();
    if (sub == 0) {
        g_pvm[row][blockIdx.x] = m;
        g_pvs[row][blockIdx.x] = ssum;
#pragma unroll
        for (int j = 0; j < 8; j++) {
            g_p8v[row][blockIdx.x][j] = svv[tid * 8 + j];
            g_p8i[row][blockIdx.x][j] = sii[tid * 8 + j];
        }
    }
}

// ---------------- per-step 4: merge (LSE + top-8 + beam update + history) ----------------
__global__ __launch_bounds__(256) void merge_kernel(int t, const int* __restrict__ eosp) {
    __shared__ float sv[2048]; __shared__ int si[2048];
    __shared__ float s_val[8]; __shared__ int s_tok[8], s_wk[8];
    int b = blockIdx.x, tid = threadIdx.x;
    int s = tid >> 5, lane = tid & 31;
    int eos = eosp[0];

    INS_DECL
    if (t == 0) {
        if (s == 0) {
            int row = b;
            float M = -FLT_MAX;
            for (int vt = lane; vt < NVT; vt += 32) M = fmaxf(M, g_pvm[row][vt]);
#pragma unroll
            for (int o = 16; o >= 1; o >>= 1) M = fmaxf(M, __shfl_xor_sync(0xFFFFFFFFu, M, o));
            float S = 0.f;
            for (int vt = lane; vt < NVT; vt += 32) S += g_pvs[row][vt] * __expf(g_pvm[row][vt] - M);
#pragma unroll
            for (int o = 16; o >= 1; o >>= 1) S += __shfl_xor_sync(0xFFFFFFFFu, S, o);
            float rc = -(M + logf(S));
            for (int vt = lane; vt < NVT; vt += 32)
#pragma unroll
                for (int j = 0; j < 8; j++) INS(g_p8v[row][vt][j] + rc, g_p8i[row][vt][j]);
        }
    } else {
        int row = b * 8 + s;
        float M = -FLT_MAX;
        for (int vt = lane; vt < NVT; vt += 32) M = fmaxf(M, g_pvm[row][vt]);
#pragma unroll
        for (int o = 16; o >= 1; o >>= 1) M = fmaxf(M, __shfl_xor_sync(0xFFFFFFFFu, M, o));
        float S = 0.f;
        for (int vt = lane; vt < NVT; vt += 32) S += g_pvs[row][vt] * __expf(g_pvm[row][vt] - M);
#pragma unroll
        for (int o = 16; o >= 1; o >>= 1) S += __shfl_xor_sync(0xFFFFFFFFu, S, o);
        float rc = g_prevvals[row] - (M + logf(S));
        if (g_prevtok[row] == eos) {
            if (lane == 0) INS(0.0f, s * VV + eos);
        } else {
            for (int vt = lane; vt < NVT; vt += 32)
#pragma unroll
                for (int j = 0; j < 8; j++) INS(g_p8v[row][vt][j] + rc, s * VV + g_p8i[row][vt][j]);
        }
    }
#pragma unroll
    for (int j = 0; j < 8; j++) { sv[tid * 8 + j] = lv[j]; si[tid * 8 + j] = li[j]; }
    __syncthreads();
    merge_lists(sv, si, tid, 128);

    if (tid < 8) {
        float v = sv[tid]; int id = si[tid];
        int tok = (t == 0) ? id : (id % VV);
        int wk  = (t == 0) ? 0  : (id / VV);
        s_val[tid] = v; s_tok[tid] = tok; s_wk[tid] = wk;
        int row = b * 8 + tid;
        g_prevvals[row] = v; g_prevtok[row] = tok; g_last[row] = tok;
        g_which[row] = (t == 0) ? b : (b * 8 + wk);
    }
    __syncthreads();

    if (t == 0) {
        for (int i = tid; i < 8 * TT; i += 256) {
            int k = i >> 6, st = i & 63;
            g_lph[0][(b * 8 + k) * TT + st] = (st == 0) ? s_val[k] : 0.0f;
            g_tkh[0][(b * 8 + k) * TT + st] = (st == 0) ? s_tok[k] : 0;
        }
    } else {
        int nb = t & 1, ob = nb ^ 1;
        for (int i = tid; i < 8 * TT; i += 256) {
            int k = i >> 6, st = i & 63;
            int dst = (b * 8 + k) * TT + st;
            int srcrow = b * 8 + s_wk[k];
            float lp; int tk;
            if (st < t)       { lp = g_lph[ob][srcrow * TT + st]; tk = g_tkh[ob][srcrow * TT + st]; }
            else if (st == t) { lp = s_val[k]; tk = s_tok[k]; }
            else              { lp = 0.0f;     tk = 0; }
            g_lph[nb][dst] = lp; g_tkh[nb][dst] = tk;
        }
    }
}

// ---------------- output ----------------
__global__ void fin_kernel(float* __restrict__ out, int n) {
    int i = blockIdx.x * blockDim.x + threadIdx.x;
    if (i >= n) return;
    if (i < NR * TT)          out[i] = g_lph[1][i];
    else if (i < 2 * NR * TT) out[i] = (float)g_tkh[1][i - NR * TT];
    else                      out[i] = 0.0f;
}

// ---------------- launch ----------------
extern "C" void kernel_launch(void* const* d_in, const int* in_sizes, int n_in,
                              void* d_out, int out_size) {
    const float* encoded   = (const float*)d_in[0];
    const float* embedding = (const float*)d_in[1];
    const float* W_ih      = (const float*)d_in[2];
    const float* W_hh      = (const float*)d_in[3];
    const float* b_ih      = (const float*)d_in[4];
    const float* b_hh      = (const float*)d_in[5];
    const float* W_out     = (const float*)d_in[6];
    const float* b_out     = (const float*)d_in[7];
    const int*   bos       = (const int*)d_in[8];
    const int*   eos       = (const int*)d_in[9];

    cudaFuncSetAttribute(logits_kernel,  cudaFuncAttributeMaxDynamicSharedMemorySize, LG_SMEM);
    cudaFuncSetAttribute(grugemm_kernel, cudaFuncAttributeMaxDynamicSharedMemorySize, GG_SMEM);

    conv_kernel<<<1024, 256>>>(W_out);
    wpack_ih_kernel<<<512, 256>>>(W_ih);
    wpack_hh_kernel<<<1024, 256>>>(W_hh);
    init_kernel<<<1, 32>>>(bos);

    for (int t = 0; t < TT; t++) {
        grugemm_kernel<<<144, 128, GG_SMEM>>>(t, encoded, embedding);
        gruelem_kernel<<<128, 256>>>(t, encoded, b_ih, b_hh);
        logits_kernel<<<250, 128, LG_SMEM>>>(b_out);
        merge_kernel<<<BB, 256>>>(t, eos);
    }
    fin_kernel<<<(out_size + 255) / 256, 256>>>((float*)d_out, out_size);
}